// round 3
// baseline (speedup 1.0000x reference)
#include <cuda_runtime.h>
#include <math.h>

#define BB 2
#define SS 2048
#define DD 1024
#define HH 16
#define DH 64
#define MROWS (BB*SS)   // 4096

// Scratch: Q and K in [B,H,S,dh] layout (16 MB each)
__device__ float g_Q[BB*HH*SS*DH];
__device__ float g_K[BB*HH*SS*DH];

__device__ __forceinline__ float logsig(float x) {
    // numerically stable log(sigmoid(x)) = min(x,0) - log1p(exp(-|x|))
    return fminf(x, 0.0f) - log1pf(expf(-fabsf(x)));
}

// ---------------------------------------------------------------------------
// GEMM: C[m,n] = sum_k A[m,k]*W[k,n] + bias[n], scattered to dst[b][h][s][d]
// BM=BN=128, BK=16, 256 threads, 8x8 microtile per thread.
// ---------------------------------------------------------------------------
__global__ __launch_bounds__(256) void qk_gemm(
    const float* __restrict__ A, const float* __restrict__ W,
    const float* __restrict__ bias, float* __restrict__ dst)
{
    __shared__ float As[16][128];   // [k][m] (A transposed on load)
    __shared__ float Bs[16][128];   // [k][n]

    const int tid = threadIdx.x;
    const int m0 = blockIdx.y * 128;
    const int n0 = blockIdx.x * 128;
    const int ty = tid >> 4;        // 0..15
    const int tx = tid & 15;        // 0..15

    float acc[8][8];
    #pragma unroll
    for (int i = 0; i < 8; i++)
        #pragma unroll
        for (int j = 0; j < 8; j++) acc[i][j] = 0.0f;

    for (int k0 = 0; k0 < DD; k0 += 16) {
        // Load A tile: 128 rows x 16 cols = 512 float4
        #pragma unroll
        for (int i = 0; i < 2; i++) {
            int idx = tid + i * 256;          // 0..511
            int row = idx >> 2;
            int c4  = idx & 3;
            float4 v = *(const float4*)&A[(size_t)(m0 + row) * DD + k0 + c4 * 4];
            As[c4*4+0][row] = v.x;
            As[c4*4+1][row] = v.y;
            As[c4*4+2][row] = v.z;
            As[c4*4+3][row] = v.w;
        }
        // Load W tile: 16 rows x 128 cols = 512 float4
        #pragma unroll
        for (int i = 0; i < 2; i++) {
            int idx = tid + i * 256;          // 0..511
            int row = idx >> 5;               // 0..15
            int c4  = idx & 31;               // 0..31
            *(float4*)&Bs[row][c4*4] =
                *(const float4*)&W[(size_t)(k0 + row) * DD + n0 + c4 * 4];
        }
        __syncthreads();

        #pragma unroll
        for (int k = 0; k < 16; k++) {
            float a[8], b[8];
            #pragma unroll
            for (int i = 0; i < 8; i += 4) {
                float4 v = *(const float4*)&As[k][ty*8 + i];
                a[i] = v.x; a[i+1] = v.y; a[i+2] = v.z; a[i+3] = v.w;
            }
            #pragma unroll
            for (int j = 0; j < 8; j += 4) {
                float4 v = *(const float4*)&Bs[k][tx*8 + j];
                b[j] = v.x; b[j+1] = v.y; b[j+2] = v.z; b[j+3] = v.w;
            }
            #pragma unroll
            for (int i = 0; i < 8; i++)
                #pragma unroll
                for (int j = 0; j < 8; j++)
                    acc[i][j] = fmaf(a[i], b[j], acc[i][j]);
        }
        __syncthreads();
    }

    // Epilogue: add bias, scatter to [B,H,S,dh]
    #pragma unroll
    for (int i = 0; i < 8; i++) {
        int m = m0 + ty*8 + i;
        int b = m >> 11;            // m / S
        int s = m & (SS - 1);       // m % S
        #pragma unroll
        for (int j = 0; j < 8; j++) {
            int n = n0 + tx*8 + j;
            int h = n >> 6;         // n / DH
            int d = n & (DH - 1);   // n % DH
            dst[(((size_t)b * HH + h) * SS + s) * DH + d] = acc[i][j] + bias[n];
        }
    }
}

// ---------------------------------------------------------------------------
// Pointwise: K = logsig(logsig(Q) + Q + Kraw), in place on g_K.
// ---------------------------------------------------------------------------
__global__ __launch_bounds__(256) void fuse_k()
{
    int i = blockIdx.x * blockDim.x + threadIdx.x;   // float4 index
    float4 q  = ((const float4*)g_Q)[i];
    float4 kr = ((const float4*)g_K)[i];
    float4 o;
    o.x = logsig(logsig(q.x) + q.x + kr.x);
    o.y = logsig(logsig(q.y) + q.y + kr.y);
    o.z = logsig(logsig(q.z) + q.z + kr.z);
    o.w = logsig(logsig(q.w) + q.w + kr.w);
    ((float4*)g_K)[i] = o;
}

// ---------------------------------------------------------------------------
// Attention: one query row per thread, 128 rows per block.
// scores = -(q . k)/8, mask on QUERY rows, softmax over keys, value = Q.
// Online softmax with rare-rescale branch; K/Q key-tiles staged in shared.
// ---------------------------------------------------------------------------
__global__ __launch_bounds__(128) void attn(
    const int* __restrict__ mask, float* __restrict__ out)
{
    __shared__ float Kt[64][DH];
    __shared__ float Qt[64][DH];

    const int bh = blockIdx.y;          // b*H + h
    const int b  = bh >> 4;
    const int h  = bh & (HH - 1);
    const int srow = blockIdx.x * 128 + threadIdx.x;

    const float* __restrict__ Qbh = g_Q + (size_t)bh * SS * DH;
    const float* __restrict__ Kbh = g_K + (size_t)bh * SS * DH;

    float q[DH];
    #pragma unroll
    for (int d = 0; d < DH; d += 4) {
        float4 v = *(const float4*)&Qbh[(size_t)srow * DH + d];
        q[d] = v.x; q[d+1] = v.y; q[d+2] = v.z; q[d+3] = v.w;
    }
    const bool masked = (mask[b * SS + srow] == 0);

    float mx = -1e30f, l = 0.0f;
    float acc[DH];
    #pragma unroll
    for (int d = 0; d < DH; d++) acc[d] = 0.0f;

    for (int t0 = 0; t0 < SS; t0 += 64) {
        __syncthreads();
        // Stage 64 keys: K tile + Q-as-value tile (4096 floats each)
        #pragma unroll
        for (int i = 0; i < 8; i++) {
            int idx = threadIdx.x + i * 128;   // 0..1023 float4 slots
            ((float4*)Kt)[idx] = ((const float4*)(Kbh + (size_t)t0 * DH))[idx];
            ((float4*)Qt)[idx] = ((const float4*)(Qbh + (size_t)t0 * DH))[idx];
        }
        __syncthreads();

        #pragma unroll 2
        for (int j = 0; j < 64; j++) {
            float s0 = 0.f, s1 = 0.f, s2 = 0.f, s3 = 0.f;
            #pragma unroll
            for (int d = 0; d < DH; d += 4) {
                float4 kv = *(const float4*)&Kt[j][d];
                s0 = fmaf(q[d+0], kv.x, s0);
                s1 = fmaf(q[d+1], kv.y, s1);
                s2 = fmaf(q[d+2], kv.z, s2);
                s3 = fmaf(q[d+3], kv.w, s3);
            }
            float sc = -((s0 + s1) + (s2 + s3)) * 0.125f;
            if (masked) sc = -10000.0f;

            if (sc > mx) {
                float corr = __expf(mx - sc);
                mx = sc;
                l *= corr;
                #pragma unroll
                for (int d = 0; d < DH; d++) acc[d] *= corr;
            }
            float p = __expf(sc - mx);
            l += p;
            #pragma unroll
            for (int d = 0; d < DH; d += 4) {
                float4 v = *(const float4*)&Qt[j][d];
                acc[d+0] = fmaf(p, v.x, acc[d+0]);
                acc[d+1] = fmaf(p, v.y, acc[d+1]);
                acc[d+2] = fmaf(p, v.z, acc[d+2]);
                acc[d+3] = fmaf(p, v.w, acc[d+3]);
            }
        }
    }

    const float inv = 1.0f / l;
    float* __restrict__ orow = out + ((size_t)b * SS + srow) * (HH * DH) + h * DH;
    #pragma unroll
    for (int d = 0; d < DH; d += 4) {
        float4 v;
        v.x = acc[d+0] * inv;
        v.y = acc[d+1] * inv;
        v.z = acc[d+2] * inv;
        v.w = acc[d+3] * inv;
        *(float4*)&orow[d] = v;
    }
}

// ---------------------------------------------------------------------------
extern "C" void kernel_launch(void* const* d_in, const int* in_sizes, int n_in,
                              void* d_out, int out_size)
{
    const float* hs   = (const float*)d_in[0];
    const int*   mask = (const int*)  d_in[1];
    const float* Wq   = (const float*)d_in[2];
    const float* bq   = (const float*)d_in[3];
    const float* Wk   = (const float*)d_in[4];
    const float* bk   = (const float*)d_in[5];
    float* out = (float*)d_out;

    void *qptr = nullptr, *kptr = nullptr;
    cudaGetSymbolAddress(&qptr, g_Q);
    cudaGetSymbolAddress(&kptr, g_K);

    dim3 ggrid(DD / 128, MROWS / 128);           // (8, 32)
    qk_gemm<<<ggrid, 256>>>(hs, Wq, bq, (float*)qptr);
    qk_gemm<<<ggrid, 256>>>(hs, Wk, bk, (float*)kptr);

    int nvec4 = (BB * HH * SS * DH) / 4;         // 1M float4
    fuse_k<<<nvec4 / 256, 256>>>();

    dim3 agrid(SS / 128, BB * HH);               // (16, 32)
    attn<<<agrid, 128>>>(mask, out);
}